// round 16
// baseline (speedup 1.0000x reference)
#include <cuda_runtime.h>
#include <stdint.h>

#define IN_DIM   4096
#define OUT_DIM  1024
#define RB       64      // x rows per block (2 per lane, interleaved as float2)
#define KT       512     // K columns per phase
#define NPH      8       // IN_DIM / KT
#define TPB      1024
#define OPW      16      // outputs per warp
#define OSPLIT   2       // output groups
#define OPB      (OUT_DIM / OSPLIT)   // 512 outputs per block
#define NSLICE   (NPH * OSPLIT)       // 16 (phase, outgroup) slices
#define SLICE_CAP 4096   // entries per slice (avg ~2560, huge margin)
#define CSTRIDE_B 264    // bytes per tile column: 32 float2 (rows L,L+32) + 8B pad
#define TILE_BYTES (KT * CSTRIDE_B)          // 135168
#define TAB_OFF   TILE_BYTES                 // staged slice (16B aligned)
#define OFF_OFF   (TAB_OFF + SLICE_CAP * 8)  // 167936 (16B aligned)
#define SMEM_BYTES (OFF_OFF + (OPB + 4) * 4) // 170000
#define EP_STRIDE 513    // epilogue staging stride (floats); 513%32==1 conflict-free

// Phase-major packed sparse table (rebuilt every launch; deterministic).
// Slice s = p*OSPLIT + og: entries of phase p for outputs [og*512, og*512+512).
// Entry = { byte offset (c_local * 264) into interleaved tile, fp32 value bits }.
__device__ int  g_cnt[NPH * OUT_DIM];
__device__ int  g_soff[NSLICE][OPB + 1];
__device__ int2 g_ptab[NSLICE * SLICE_CAP];

// ---------------------------------------------------------------------------
// Prep 1: nonzero count per (output o, phase q). Warp q owns cols [q*512,+512).
// ---------------------------------------------------------------------------
__global__ void __launch_bounds__(256) count_kernel(const float* __restrict__ Phi) {
    const int o = blockIdx.x, t = threadIdx.x, q = t >> 5, u = t & 31;
    const float* row = Phi + (size_t)o * IN_DIM;
    int cnt = 0;
#pragma unroll
    for (int k = 0; k < 16; k++) cnt += (row[q * KT + k * 32 + u] != 0.0f);
#pragma unroll
    for (int d = 16; d; d >>= 1) cnt += __shfl_down_sync(0xffffffffu, cnt, d);
    if (u == 0) g_cnt[q * OUT_DIM + o] = cnt;
}

// ---------------------------------------------------------------------------
// Prep 2: exclusive scan of counts within each (phase, outgroup) slice.
// ---------------------------------------------------------------------------
__global__ void __launch_bounds__(OPB) scan_kernel() {
    const int s = blockIdx.x;          // s = p*OSPLIT + og
    const int p = s >> 1, og = s & 1, t = threadIdx.x;
    __shared__ int sh[OPB];
    int c = g_cnt[p * OUT_DIM + og * OPB + t];
    sh[t] = c;
    __syncthreads();
#pragma unroll
    for (int d = 1; d < OPB; d <<= 1) {
        int v = (t >= d) ? sh[t - d] : 0;
        __syncthreads();
        sh[t] += v;
        __syncthreads();
    }
    g_soff[s][t] = min(sh[t] - c, SLICE_CAP);
    if (t == OPB - 1) g_soff[s][OPB] = min(sh[t], SLICE_CAP);
}

// ---------------------------------------------------------------------------
// Prep 3: fill packed table (deterministic lane-k order); offset = c_local*264.
// ---------------------------------------------------------------------------
__global__ void __launch_bounds__(256) fill_kernel(const float* __restrict__ Phi) {
    const int o = blockIdx.x, t = threadIdx.x, q = t >> 5, u = t & 31;
    const int og = (o >= OPB) ? 1 : 0;
    const int ol = o - og * OPB;
    const int s  = q * OSPLIT + og;
    const float* row = Phi + (size_t)o * IN_DIM;

    float rv[16];
    int cnt = 0;
#pragma unroll
    for (int k = 0; k < 16; k++) { rv[k] = row[q * KT + k * 32 + u]; cnt += (rv[k] != 0.0f); }

    int ex = cnt;
#pragma unroll
    for (int d = 1; d < 32; d <<= 1) {
        int v = __shfl_up_sync(0xffffffffu, ex, d);
        if (u >= d) ex += v;
    }
    ex -= cnt;   // exclusive prefix over lanes

    int dst = g_soff[s][ol] + ex;
#pragma unroll
    for (int k = 0; k < 16; k++) {
        float v = rv[k];
        if (v != 0.0f) {
            if (dst < SLICE_CAP) {
                int c_local = k * 32 + u;           // 0..511
                g_ptab[s * SLICE_CAP + dst] =
                    make_int2(c_local * CSTRIDE_B, __float_as_int(v));
            }
            dst++;
        }
    }
}

// ---------------------------------------------------------------------------
// Main: sparse out = x @ Phi^T. Block: 64 x-rows, 512 outputs (warp w -> 16
// contiguous), 8 K-phases of 512 cols. Tile column c holds 32 float2:
// slot L = (x[row L][c], x[row L+32][c]). One warp-uniform entry ->
// IADD + LDS.64 (contiguous 256B, 2 conflict-free wavefronts) + 2 FFMA.
// blockIdx bit0 = output group (paired blocks share x rows -> L2 reuse).
// ---------------------------------------------------------------------------
__global__ void __launch_bounds__(TPB, 1) spjl_kernel(
    const float* __restrict__ x, float* __restrict__ out, int nrows) {
    extern __shared__ float xs[];                       // interleaved tile
    int2* st_tab = (int2*)((char*)xs + TAB_OFF);
    int*  st_off = (int*)((char*)xs + OFF_OFF);

    const int tid = threadIdx.x;
    const int w   = tid >> 5;
    const int L   = tid & 31;
    const int rg  = blockIdx.x >> 1;
    const int og  = blockIdx.x & 1;
    const size_t n0 = (size_t)rg * RB;
    const int olb = w * OPW;                            // warp's first local output

    float acc0[OPW], acc1[OPW];
#pragma unroll
    for (int io = 0; io < OPW; io++) { acc0[io] = 0.0f; acc1[io] = 0.0f; }

    const char* xpair = (const char*)xs + L * 8;        // lane's float2 slot base

    for (int p = 0; p < NPH; p++) {
        const int s = p * OSPLIT + og;
        const int len = g_soff[s][OPB];
        __syncthreads();   // previous phase readers done before overwrite

        // Stage x tile interleaved: thread (g, c) loads rows n0+g and n0+g+32
        // at col c (coalesced scalar LDG x2), one STS.64.
#pragma unroll
        for (int it = 0; it < (RB * KT / 2) / TPB; it++) {
            int un = tid + it * TPB;
            int c  = un & (KT - 1);
            int g  = un >> 9;              // 0..31
            size_t gr = n0 + g;
            const float* xp = x + gr * IN_DIM + (size_t)p * KT + c;
            float v0 = 0.0f, v1 = 0.0f;
            if (gr + 32 < (size_t)nrows) {
                v0 = xp[0]; v1 = xp[32 * IN_DIM];
            } else {
                if (gr < (size_t)nrows)      v0 = xp[0];
                if (gr + 32 < (size_t)nrows) v1 = xp[32 * IN_DIM];
            }
            *(float2*)((char*)xs + c * CSTRIDE_B + g * 8) = make_float2(v0, v1);
        }
        // Stage table slice (int4 copies; SLICE_CAP-sized source, safe to round up).
        {
            const int4* src = (const int4*)(g_ptab + s * SLICE_CAP);
            int4*       dst = (int4*)st_tab;
            int n4 = (len + 1) >> 1;
            for (int i = tid; i < n4; i += TPB) dst[i] = src[i];
        }
        if (tid <= OPB) st_off[tid] = g_soff[s][tid];
        __syncthreads();

        int jb = st_off[olb];
#pragma unroll
        for (int io = 0; io < OPW; io++) {
            const int je = st_off[olb + io + 1];
            float a0 = acc0[io], a1 = acc1[io];
            for (int j = jb; j < je; j++) {
                int2 e = st_tab[j];                         // warp-uniform broadcast
                float phv = __int_as_float(e.y);
                float2 xv = *(const float2*)(xpair + e.x);  // rows L, L+32
                a0 = fmaf(phv, xv.x, a0);
                a1 = fmaf(phv, xv.y, a1);
            }
            acc0[io] = a0; acc1[io] = a1;
            jb = je;
        }
    }

    __syncthreads();
    // Stage results (alias tile); bank = (row + col) % 32 -> conflict-free.
#pragma unroll
    for (int io = 0; io < OPW; io++) {
        xs[L        * EP_STRIDE + olb + io] = acc0[io];
        xs[(L + 32) * EP_STRIDE + olb + io] = acc1[io];
    }
    __syncthreads();
    // Coalesced store of 64 rows x 512 outputs.
#pragma unroll
    for (int it = 0; it < (RB * OPB) / TPB; it++) {
        int i  = tid + it * TPB;
        int rr = i >> 9;
        int k  = i & (OPB - 1);
        size_t gr = n0 + rr;
        if (gr < (size_t)nrows)
            out[gr * OUT_DIM + og * OPB + k] = xs[rr * EP_STRIDE + k];
    }
}

extern "C" void kernel_launch(void* const* d_in, const int* in_sizes, int n_in,
                              void* d_out, int out_size) {
    const float* x   = (const float*)d_in[0];   // [N, 4096] fp32
    const float* Phi = (const float*)d_in[1];   // [1024, 4096] fp32
    float* out = (float*)d_out;                 // [N, 1024] fp32

    const int nrows = in_sizes[0] / IN_DIM;              // 16384
    const int grid  = ((nrows + RB - 1) / RB) * OSPLIT;  // 512

    cudaFuncSetAttribute(spjl_kernel,
                         cudaFuncAttributeMaxDynamicSharedMemorySize, SMEM_BYTES);

    count_kernel<<<OUT_DIM, 256>>>(Phi);
    scan_kernel<<<NSLICE, OPB>>>();
    fill_kernel<<<OUT_DIM, 256>>>(Phi);
    spjl_kernel<<<grid, TPB, SMEM_BYTES>>>(x, out, nrows);
}